// round 12
// baseline (speedup 1.0000x reference)
#include <cuda_runtime.h>
#include <cuda_fp16.h>
#include <cstdint>

#define NB 16

static __device__ float   g_style[NB * 512];
static __device__ float   g_wsq[512 * 512];
static __device__ float   g_demod[NB * 512];
static __device__ __half2 g_V[(size_t)16 * 256 * 16384];  // [t][kk][m]
static __device__ __half2 g_U[(size_t)16 * 256 * 512];    // [t][kk][o]
static __device__ __half2 g_P[(size_t)8 * 256 * 16384];   // [ti*2+c][opair][m]

// ---------------- small prep ----------------
__global__ void style_kernel(const float* __restrict__ w, const float* __restrict__ mw,
                             const float* __restrict__ mb) {
    __shared__ float sw[512];
    int b = blockIdx.x, c = threadIdx.x;
    sw[c] = w[b * 512 + c];
    __syncthreads();
    float acc = 0.f;
    const float* row = mw + c * 512;
#pragma unroll 8
    for (int d = 0; d < 512; d++) acc += sw[d] * row[d];
    g_style[b * 512 + c] = acc * 0.04419417382415922f + mb[c];
}
__global__ void wsq_kernel(const float* __restrict__ weight) {
    int o = blockIdx.x, c = threadIdx.x;
    const float* p = weight + (o * 512 + c) * 9;
    float s = 0.f;
#pragma unroll
    for (int t = 0; t < 9; t++) { float v = p[t]; s += v * v; }
    g_wsq[o * 512 + c] = s;
}
__global__ void demod_kernel() {
    int gid = blockIdx.x * blockDim.x + threadIdx.x;
    int o = gid >> 4, b = gid & 15;
    const float* wq = g_wsq + o * 512;
    const float* st = g_style + b * 512;
    float s = 0.f;
#pragma unroll 8
    for (int c = 0; c < 512; c++) { float t = st[c]; s += wq[c] * t * t; }
    g_demod[b * 512 + o] = rsqrtf(s * (1.f / 4608.f) + 1e-8f);
}

// ---------------- U = G w G^T (R10 version) ----------------
__global__ void ut_kernel(const float* __restrict__ weight) {
    int idx = blockIdx.x * 256 + threadIdx.x;
    int o = idx & 511, kk = idx >> 9;
    const float WG = 0.014731391274719739f;
    float u[2][4][4];
#pragma unroll
    for (int ch = 0; ch < 2; ch++) {
        const float* wp = weight + ((size_t)o * 512 + 2 * kk + ch) * 9;
        float tmp[4][3];
#pragma unroll
        for (int c = 0; c < 3; c++) {
            float w0 = wp[c], w1 = wp[3 + c], w2 = wp[6 + c];
            tmp[0][c] = w0;
            tmp[1][c] = 0.5f * (w0 + w1 + w2);
            tmp[2][c] = 0.5f * (w0 - w1 + w2);
            tmp[3][c] = w2;
        }
#pragma unroll
        for (int i = 0; i < 4; i++) {
            float t0 = tmp[i][0], t1 = tmp[i][1], t2 = tmp[i][2];
            u[ch][i][0] = t0 * WG;
            u[ch][i][1] = 0.5f * (t0 + t1 + t2) * WG;
            u[ch][i][2] = 0.5f * (t0 - t1 + t2) * WG;
            u[ch][i][3] = t2 * WG;
        }
    }
#pragma unroll
    for (int t = 0; t < 16; t++)
        g_U[((size_t)t * 256 + kk) * 512 + o] =
            __floats2half2_rn(u[0][t >> 2][t & 3], u[1][t >> 2][t & 3]);
}

// ---------------- V = B^T (style*x) B : 4 tiles/thread ----------------
__global__ void __launch_bounds__(256) vt_kernel(const float* __restrict__ x) {
    int idx = blockIdx.x * 256 + threadIdx.x;
    int q  = idx & 7;
    int ty = (idx >> 3) & 31;
    int kk = (idx >> 8) & 255;
    int b  = idx >> 16;
    float s[2];
    s[0] = g_style[b * 512 + 2 * kk];
    s[1] = g_style[b * 512 + 2 * kk + 1];

    float f0[16][4];
    __half2 hv[16][4];

#pragma unroll
    for (int ch = 0; ch < 2; ch++) {
        const float* xp = x + ((size_t)(b * 512 + 2 * kk + ch)) * 4096;
        float d[4][10];
        int y0 = 2 * ty - 1;
        int xl = 8 * q - 1;
#pragma unroll
        for (int r = 0; r < 4; r++) {
            int y = y0 + r;
            bool vy = (y >= 0) && (y < 64);
            const float* row = xp + y * 64;
            float4 A = make_float4(0.f, 0.f, 0.f, 0.f), B = A;
            if (vy) {
                A = *reinterpret_cast<const float4*>(row + 8 * q);
                B = *reinterpret_cast<const float4*>(row + 8 * q + 4);
            }
            float sc = s[ch];
            d[r][0] = (vy && q > 0) ? row[xl] * sc : 0.f;
            d[r][1] = A.x * sc; d[r][2] = A.y * sc; d[r][3] = A.z * sc; d[r][4] = A.w * sc;
            d[r][5] = B.x * sc; d[r][6] = B.y * sc; d[r][7] = B.z * sc; d[r][8] = B.w * sc;
            d[r][9] = (vy && q < 7) ? row[8 * q + 8] * sc : 0.f;
        }
        float p[4][10];
#pragma unroll
        for (int c = 0; c < 10; c++) {
            p[0][c] = d[0][c] - d[2][c];
            p[1][c] = d[1][c] + d[2][c];
            p[2][c] = d[2][c] - d[1][c];
            p[3][c] = d[1][c] - d[3][c];
        }
#pragma unroll
        for (int dt = 0; dt < 4; dt++) {
            int cl = 2 * dt;
#pragma unroll
            for (int i = 0; i < 4; i++) {
                float v0 = p[i][cl]     - p[i][cl + 2];
                float v1 = p[i][cl + 1] + p[i][cl + 2];
                float v2 = p[i][cl + 2] - p[i][cl + 1];
                float v3 = p[i][cl + 1] - p[i][cl + 3];
                if (ch == 0) {
                    f0[4 * i + 0][dt] = v0; f0[4 * i + 1][dt] = v1;
                    f0[4 * i + 2][dt] = v2; f0[4 * i + 3][dt] = v3;
                } else {
                    hv[4 * i + 0][dt] = __floats2half2_rn(f0[4 * i + 0][dt], v0);
                    hv[4 * i + 1][dt] = __floats2half2_rn(f0[4 * i + 1][dt], v1);
                    hv[4 * i + 2][dt] = __floats2half2_rn(f0[4 * i + 2][dt], v2);
                    hv[4 * i + 3][dt] = __floats2half2_rn(f0[4 * i + 3][dt], v3);
                }
            }
        }
    }
    size_t m0 = (size_t)b * 1024 + ty * 32 + 4 * q;
#pragma unroll
    for (int t = 0; t < 16; t++)
        *reinterpret_cast<uint4*>(&g_V[((size_t)t * 256 + kk) * 16384 + m0]) =
            *reinterpret_cast<const uint4*>(hv[t]);
}

// ---------------- Winograd GEMM: 4 tj per CTA, fused column transform ----------------
__device__ __forceinline__ void mma16816(float& c0, float& c1, float& c2, float& c3,
                                         uint32_t a0, uint32_t a1, uint32_t a2, uint32_t a3,
                                         uint32_t b0, uint32_t b1) {
    asm volatile(
        "mma.sync.aligned.m16n8k16.row.col.f32.f16.f16.f32 "
        "{%0,%1,%2,%3}, {%4,%5,%6,%7}, {%8,%9}, {%0,%1,%2,%3};\n"
        : "+f"(c0), "+f"(c1), "+f"(c2), "+f"(c3)
        : "r"(a0), "r"(a1), "r"(a2), "r"(a3), "r"(b0), "r"(b1));
}
__device__ __forceinline__ void cp16(uint32_t dst, const void* src) {
    asm volatile("cp.async.cg.shared.global [%0], [%1], 16;\n" :: "r"(dst), "l"(src));
}
__device__ __forceinline__ void cp_commit() {
    asm volatile("cp.async.commit_group;\n" ::: "memory");
}

#define AS 72                 // half2 per kk row (64 used + 8 pad)
#define TS (8 * AS)           // 576 half2 per t-block
#define HSTG (8 * AS * 8)     // 4608 half2 = A(2304) + B(2304) per stage

__global__ void __launch_bounds__(128) wg_kernel() {
    extern __shared__ __align__(16) __half2 sm[];
    const int ti  = blockIdx.z;               // Winograd row 0..3
    const int o0  = blockIdx.x * 64;
    const int MB0 = blockIdx.y * 64;
    const int tid = threadIdx.x, w = tid >> 5, lane = tid & 31;
    const int g = lane >> 2, t4 = lane & 3;
    const int wm = (w & 1) * 32;              // warp m offset (m32)
    const int wo = (w >> 1) * 32;             // warp o offset (n32)
    const uint32_t sb = (uint32_t)__cvta_generic_to_shared(sm);

    float acc[4][8][4];                        // [tj][ms*4+nc][reg]
#pragma unroll
    for (int t = 0; t < 4; t++)
#pragma unroll
        for (int i = 0; i < 8; i++)
#pragma unroll
            for (int j = 0; j < 4; j++) acc[t][i][j] = 0.f;

    auto load = [&](int kc, int st) {
        uint32_t base = sb + (uint32_t)(st * HSTG) * 4u;
#pragma unroll
        for (int i = 0; i < 8; i++) {
            int idx = tid + i * 128;           // 0..1023
            int half = idx >> 9;               // 0 = A (V), 1 = B (U)
            int j = idx & 511;
            int t = j >> 7, kk = (j >> 4) & 7, v = j & 15;
            uint32_t dst = base + (uint32_t)(half * 2304 + t * TS + kk * AS) * 4u + v * 16u;
            size_t slice = ((size_t)((ti * 4 + t) * 256 + kc * 8 + kk));
            if (half == 0)
                cp16(dst, g_V + slice * 16384 + MB0 + v * 4);
            else
                cp16(dst, g_U + slice * 512 + o0 + v * 4);
        }
    };

    auto compute = [&](int c) {
        const __half2* As = sm + (c & 3) * HSTG;
        const __half2* Bs = As + 2304;
#pragma unroll
        for (int t = 0; t < 4; t++) {
            uint32_t a[2][4];
#pragma unroll
            for (int ms = 0; ms < 2; ms++) {
                const __half2* ab = As + t * TS + t4 * AS + wm + ms * 16 + g;
                a[ms][0] = *reinterpret_cast<const uint32_t*>(ab);
                a[ms][1] = *reinterpret_cast<const uint32_t*>(ab + 8);
                a[ms][2] = *reinterpret_cast<const uint32_t*>(ab + 4 * AS);
                a[ms][3] = *reinterpret_cast<const uint32_t*>(ab + 4 * AS + 8);
            }
            uint32_t bf[4][2];
#pragma unroll
            for (int nc = 0; nc < 4; nc++) {
                const __half2* bb = Bs + t * TS + t4 * AS + wo + nc * 8 + g;
                bf[nc][0] = *reinterpret_cast<const uint32_t*>(bb);
                bf[nc][1] = *reinterpret_cast<const uint32_t*>(bb + 4 * AS);
            }
#pragma unroll
            for (int nc = 0; nc < 4; nc++)
#pragma unroll
                for (int ms = 0; ms < 2; ms++) {
                    float* cc = acc[t][ms * 4 + nc];
                    mma16816(cc[0], cc[1], cc[2], cc[3],
                             a[ms][0], a[ms][1], a[ms][2], a[ms][3],
                             bf[nc][0], bf[nc][1]);
                }
        }
    };

    load(0, 0); cp_commit();
    load(1, 1); cp_commit();
    load(2, 2); cp_commit();

#pragma unroll 1
    for (int c = 0; c < 32; c++) {
        if (c <= 29)      asm volatile("cp.async.wait_group 2;\n" ::: "memory");
        else if (c == 30) asm volatile("cp.async.wait_group 1;\n" ::: "memory");
        else              asm volatile("cp.async.wait_group 0;\n" ::: "memory");
        __syncthreads();
        if (c + 3 < 32) { load(c + 3, (c + 3) & 3); cp_commit(); }
        compute(c);
    }

    // epilogue: fused column transform over tj, store P (c=0,1), fp16
#pragma unroll
    for (int ms = 0; ms < 2; ms++) {
        int m0 = MB0 + wm + ms * 16 + g;
#pragma unroll
        for (int nc = 0; nc < 4; nc++) {
            int opair = (o0 + wo + nc * 8) / 2 + t4;
            int f = ms * 4 + nc;
            float c0[4], c1[4];
#pragma unroll
            for (int k = 0; k < 4; k++) {
                c0[k] = acc[0][f][k] + acc[1][f][k] + acc[2][f][k];
                c1[k] = acc[1][f][k] - acc[2][f][k] - acc[3][f][k];
            }
            size_t p0 = ((size_t)((ti * 2 + 0) * 256 + opair)) * 16384;
            size_t p1 = ((size_t)((ti * 2 + 1) * 256 + opair)) * 16384;
            g_P[p0 + m0]     = __floats2half2_rn(c0[0], c0[1]);
            g_P[p0 + m0 + 8] = __floats2half2_rn(c0[2], c0[3]);
            g_P[p1 + m0]     = __floats2half2_rn(c1[0], c1[1]);
            g_P[p1 + m0 + 8] = __floats2half2_rn(c1[2], c1[3]);
        }
    }
}

// ---------------- output transform: row half only, 4 tiles/thread ----------------
__global__ void __launch_bounds__(256) ot_kernel(float* __restrict__ out) {
    int idx = blockIdx.x * 256 + threadIdx.x;
    int q     = idx & 7;
    int ty    = (idx >> 3) & 31;
    int opair = (idx >> 8) & 255;
    int b     = idx >> 16;
    size_t m0 = (size_t)b * 1024 + ty * 32 + 4 * q;

    uint4 z[8];
#pragma unroll
    for (int s = 0; s < 8; s++)
        z[s] = *reinterpret_cast<const uint4*>(&g_P[((size_t)s * 256 + opair) * 16384 + m0]);

    float dm[2];
    dm[0] = g_demod[b * 512 + 2 * opair];
    dm[1] = g_demod[b * 512 + 2 * opair + 1];

    float o[2][2][8];
#pragma unroll
    for (int dt = 0; dt < 4; dt++) {
        float2 F[8];
#pragma unroll
        for (int s = 0; s < 8; s++)
            F[s] = __half22float2(reinterpret_cast<const __half2*>(&z[s])[dt]);
#pragma unroll
        for (int ch = 0; ch < 2; ch++) {
            float d = dm[ch];
#pragma unroll
            for (int c = 0; c < 2; c++) {
                float P0 = ch ? F[0 * 2 + c].y : F[0 * 2 + c].x;
                float P1 = ch ? F[1 * 2 + c].y : F[1 * 2 + c].x;
                float P2 = ch ? F[2 * 2 + c].y : F[2 * 2 + c].x;
                float P3 = ch ? F[3 * 2 + c].y : F[3 * 2 + c].x;
                o[ch][0][2 * dt + c] = (P0 + P1 + P2) * d;
                o[ch][1][2 * dt + c] = (P1 - P2 - P3) * d;
            }
        }
    }

    float* base = out + ((size_t)b * 512 + 2 * opair) * 4096 + (2 * ty) * 64 + 8 * q;
#pragma unroll
    for (int ch = 0; ch < 2; ch++)
#pragma unroll
        for (int r = 0; r < 2; r++) {
            float* p = base + (size_t)ch * 4096 + r * 64;
            *reinterpret_cast<float4*>(p)     = make_float4(o[ch][r][0], o[ch][r][1],
                                                            o[ch][r][2], o[ch][r][3]);
            *reinterpret_cast<float4*>(p + 4) = make_float4(o[ch][r][4], o[ch][r][5],
                                                            o[ch][r][6], o[ch][r][7]);
        }
}

// ---------------- launch ----------------
extern "C" void kernel_launch(void* const* d_in, const int* in_sizes, int n_in,
                              void* d_out, int out_size) {
    const float* x      = (const float*)d_in[0];
    const float* w      = (const float*)d_in[1];
    const float* weight = (const float*)d_in[2];
    const float* mw     = (const float*)d_in[3];
    const float* mb     = (const float*)d_in[4];
    float* out = (float*)d_out;

    style_kernel<<<16, 512>>>(w, mw, mb);
    wsq_kernel<<<512, 512>>>(weight);
    demod_kernel<<<32, 256>>>();
    ut_kernel<<<512, 256>>>(weight);
    vt_kernel<<<4096, 256>>>(x);

    int shmem = 4 * HSTG * 4;   // 73728 B
    cudaFuncSetAttribute(wg_kernel, cudaFuncAttributeMaxDynamicSharedMemorySize, shmem);
    dim3 grid(8, 256, 4);   // (N/64, M/64, ti)
    wg_kernel<<<grid, 128, shmem>>>();

    ot_kernel<<<4096, 256>>>(out);
}

// round 13
// speedup vs baseline: 1.2262x; 1.2262x over previous
#include <cuda_runtime.h>
#include <cuda_fp16.h>
#include <cstdint>

#define NB 16

static __device__ float   g_style[NB * 512];
static __device__ float   g_wsq[512 * 512];
static __device__ float   g_demod[NB * 512];
static __device__ __half2 g_V[(size_t)16 * 256 * 16384];  // [t][kk][m]
static __device__ __half2 g_U[(size_t)16 * 256 * 512];    // [t][kk][o]
static __device__ __half2 g_Z[(size_t)16 * 256 * 16384];  // [t][opair][m]

// ---------------- prep ----------------
__global__ void style_kernel(const float* __restrict__ w, const float* __restrict__ mw,
                             const float* __restrict__ mb) {
    __shared__ float sw[512];
    int b = blockIdx.x, c = threadIdx.x;
    sw[c] = w[b * 512 + c];
    __syncthreads();
    float acc = 0.f;
    const float* row = mw + c * 512;
#pragma unroll 8
    for (int d = 0; d < 512; d++) acc += sw[d] * row[d];
    g_style[b * 512 + c] = acc * 0.04419417382415922f + mb[c];
}

// U = G w G^T ; also emits per-channel weight-square sums (fused old wsq_kernel)
__global__ void ut_kernel(const float* __restrict__ weight) {
    int idx = blockIdx.x * 256 + threadIdx.x;
    int o = idx & 511, kk = idx >> 9;
    const float WG = 0.014731391274719739f;
    float u[2][4][4];
#pragma unroll
    for (int ch = 0; ch < 2; ch++) {
        const float* wp = weight + ((size_t)o * 512 + 2 * kk + ch) * 9;
        float tmp[4][3];
        float sq = 0.f;
#pragma unroll
        for (int c = 0; c < 3; c++) {
            float w0 = wp[c], w1 = wp[3 + c], w2 = wp[6 + c];
            sq += w0 * w0 + w1 * w1 + w2 * w2;
            tmp[0][c] = w0;
            tmp[1][c] = 0.5f * (w0 + w1 + w2);
            tmp[2][c] = 0.5f * (w0 - w1 + w2);
            tmp[3][c] = w2;
        }
        g_wsq[o * 512 + 2 * kk + ch] = sq;
#pragma unroll
        for (int i = 0; i < 4; i++) {
            float t0 = tmp[i][0], t1 = tmp[i][1], t2 = tmp[i][2];
            u[ch][i][0] = t0 * WG;
            u[ch][i][1] = 0.5f * (t0 + t1 + t2) * WG;
            u[ch][i][2] = 0.5f * (t0 - t1 + t2) * WG;
            u[ch][i][3] = t2 * WG;
        }
    }
#pragma unroll
    for (int t = 0; t < 16; t++)
        g_U[((size_t)t * 256 + kk) * 512 + o] =
            __floats2half2_rn(u[0][t >> 2][t & 3], u[1][t >> 2][t & 3]);
}

// demod: one warp per (b,o), shfl reduction
__global__ void demod_kernel() {
    int wid = blockIdx.x * 8 + (threadIdx.x >> 5);   // 8192 warps
    int lane = threadIdx.x & 31;
    int b = wid & 15, o = wid >> 4;
    const float* wq = g_wsq + o * 512;
    const float* st = g_style + b * 512;
    float s = 0.f;
#pragma unroll
    for (int i = 0; i < 16; i++) {
        int c = lane + i * 32;
        float t = st[c];
        s += wq[c] * t * t;
    }
#pragma unroll
    for (int d = 16; d > 0; d >>= 1)
        s += __shfl_xor_sync(0xFFFFFFFFu, s, d);
    if (lane == 0)
        g_demod[b * 512 + o] = rsqrtf(s * (1.f / 4608.f) + 1e-8f);
}

// ---------------- V = B^T (style*x) B : 4 tiles/thread ----------------
__global__ void __launch_bounds__(256) vt_kernel(const float* __restrict__ x) {
    int idx = blockIdx.x * 256 + threadIdx.x;
    int q  = idx & 7;
    int ty = (idx >> 3) & 31;
    int kk = (idx >> 8) & 255;
    int b  = idx >> 16;
    float s[2];
    s[0] = g_style[b * 512 + 2 * kk];
    s[1] = g_style[b * 512 + 2 * kk + 1];

    float f0[16][4];
    __half2 hv[16][4];

#pragma unroll
    for (int ch = 0; ch < 2; ch++) {
        const float* xp = x + ((size_t)(b * 512 + 2 * kk + ch)) * 4096;
        float d[4][10];
        int y0 = 2 * ty - 1;
        int xl = 8 * q - 1;
#pragma unroll
        for (int r = 0; r < 4; r++) {
            int y = y0 + r;
            bool vy = (y >= 0) && (y < 64);
            const float* row = xp + y * 64;
            float4 A = make_float4(0.f, 0.f, 0.f, 0.f), B = A;
            if (vy) {
                A = *reinterpret_cast<const float4*>(row + 8 * q);
                B = *reinterpret_cast<const float4*>(row + 8 * q + 4);
            }
            float sc = s[ch];
            d[r][0] = (vy && q > 0) ? row[xl] * sc : 0.f;
            d[r][1] = A.x * sc; d[r][2] = A.y * sc; d[r][3] = A.z * sc; d[r][4] = A.w * sc;
            d[r][5] = B.x * sc; d[r][6] = B.y * sc; d[r][7] = B.z * sc; d[r][8] = B.w * sc;
            d[r][9] = (vy && q < 7) ? row[8 * q + 8] * sc : 0.f;
        }
        float p[4][10];
#pragma unroll
        for (int c = 0; c < 10; c++) {
            p[0][c] = d[0][c] - d[2][c];
            p[1][c] = d[1][c] + d[2][c];
            p[2][c] = d[2][c] - d[1][c];
            p[3][c] = d[1][c] - d[3][c];
        }
#pragma unroll
        for (int dt = 0; dt < 4; dt++) {
            int cl = 2 * dt;
#pragma unroll
            for (int i = 0; i < 4; i++) {
                float v0 = p[i][cl]     - p[i][cl + 2];
                float v1 = p[i][cl + 1] + p[i][cl + 2];
                float v2 = p[i][cl + 2] - p[i][cl + 1];
                float v3 = p[i][cl + 1] - p[i][cl + 3];
                if (ch == 0) {
                    f0[4 * i + 0][dt] = v0; f0[4 * i + 1][dt] = v1;
                    f0[4 * i + 2][dt] = v2; f0[4 * i + 3][dt] = v3;
                } else {
                    hv[4 * i + 0][dt] = __floats2half2_rn(f0[4 * i + 0][dt], v0);
                    hv[4 * i + 1][dt] = __floats2half2_rn(f0[4 * i + 1][dt], v1);
                    hv[4 * i + 2][dt] = __floats2half2_rn(f0[4 * i + 2][dt], v2);
                    hv[4 * i + 3][dt] = __floats2half2_rn(f0[4 * i + 3][dt], v3);
                }
            }
        }
    }
    size_t m0 = (size_t)b * 1024 + ty * 32 + 4 * q;
#pragma unroll
    for (int t = 0; t < 16; t++)
        *reinterpret_cast<uint4*>(&g_V[((size_t)t * 256 + kk) * 16384 + m0]) =
            *reinterpret_cast<const uint4*>(hv[t]);
}

// ---------------- Winograd GEMM: m64n64 warps, 128-thread CTAs (R10) ----------------
__device__ __forceinline__ void mma16816(float& c0, float& c1, float& c2, float& c3,
                                         uint32_t a0, uint32_t a1, uint32_t a2, uint32_t a3,
                                         uint32_t b0, uint32_t b1) {
    asm volatile(
        "mma.sync.aligned.m16n8k16.row.col.f32.f16.f16.f32 "
        "{%0,%1,%2,%3}, {%4,%5,%6,%7}, {%8,%9}, {%0,%1,%2,%3};\n"
        : "+f"(c0), "+f"(c1), "+f"(c2), "+f"(c3)
        : "r"(a0), "r"(a1), "r"(a2), "r"(a3), "r"(b0), "r"(b1));
}
__device__ __forceinline__ void cp16(uint32_t dst, const void* src) {
    asm volatile("cp.async.cg.shared.global [%0], [%1], 16;\n" :: "r"(dst), "l"(src));
}
__device__ __forceinline__ void cp_commit() {
    asm volatile("cp.async.commit_group;\n" ::: "memory");
}

#define AS_K 136
#define BS_K 136
#define STGH (8 * AS_K + 8 * BS_K)   // 2176 half2 = 8704 B per stage

__global__ void __launch_bounds__(128) wg_kernel() {
    extern __shared__ __align__(16) __half2 sm[];
    const int t   = blockIdx.z;
    const int o0  = blockIdx.y * 128;
    const int MB0 = blockIdx.x * 128;
    const int tid = threadIdx.x, w = tid >> 5, lane = tid & 31;
    const int g = lane >> 2, t4 = lane & 3;
    const int wm = (w & 1) * 64;
    const int wo = (w >> 1) * 64;
    const uint32_t sb = (uint32_t)__cvta_generic_to_shared(sm);

    float acc[32][4];
#pragma unroll
    for (int i = 0; i < 32; i++)
#pragma unroll
        for (int j = 0; j < 4; j++) acc[i][j] = 0.f;

    auto load = [&](int kc, int st) {
        uint32_t base = sb + (uint32_t)(st * STGH) * 4u;
#pragma unroll
        for (int i = 0; i < 2; i++) {
            int id2 = tid + i * 128;
            int kkL = id2 >> 5, v = id2 & 31;
            cp16(base + (uint32_t)(kkL * AS_K) * 4u + v * 16u,
                 g_V + ((size_t)(t * 256 + kc * 8 + kkL)) * 16384 + MB0 + v * 4);
        }
#pragma unroll
        for (int i = 0; i < 2; i++) {
            int id2 = tid + i * 128;
            int kkL = id2 >> 5, v = id2 & 31;
            cp16(base + (uint32_t)(8 * AS_K + kkL * BS_K) * 4u + v * 16u,
                 g_U + ((size_t)(t * 256 + kc * 8 + kkL)) * 512 + o0 + v * 4);
        }
    };
    load(0, 0); cp_commit();
    load(1, 1); cp_commit();
    load(2, 2); cp_commit();

#pragma unroll 1
    for (int c = 0; c < 32; c++) {
        if (c <= 29)      asm volatile("cp.async.wait_group 2;\n" ::: "memory");
        else if (c == 30) asm volatile("cp.async.wait_group 1;\n" ::: "memory");
        else              asm volatile("cp.async.wait_group 0;\n" ::: "memory");
        __syncthreads();
        if (c + 3 < 32) { load(c + 3, (c + 3) & 3); cp_commit(); }

        const __half2* As = sm + (c & 3) * STGH;
        const __half2* Bs = As + 8 * AS_K;

        uint32_t a[4][4];
#pragma unroll
        for (int ms = 0; ms < 4; ms++) {
            const __half2* ab = As + t4 * AS_K + wm + ms * 16 + g;
            a[ms][0] = *reinterpret_cast<const uint32_t*>(ab);
            a[ms][1] = *reinterpret_cast<const uint32_t*>(ab + 8);
            a[ms][2] = *reinterpret_cast<const uint32_t*>(ab + 4 * AS_K);
            a[ms][3] = *reinterpret_cast<const uint32_t*>(ab + 4 * AS_K + 8);
        }
        uint32_t bf[8][2];
#pragma unroll
        for (int nc = 0; nc < 8; nc++) {
            const __half2* bb = Bs + t4 * BS_K + wo + nc * 8 + g;
            bf[nc][0] = *reinterpret_cast<const uint32_t*>(bb);
            bf[nc][1] = *reinterpret_cast<const uint32_t*>(bb + 4 * BS_K);
        }
#pragma unroll
        for (int nc = 0; nc < 8; nc++)
#pragma unroll
            for (int ms = 0; ms < 4; ms++) {
                float* cc = acc[ms * 8 + nc];
                mma16816(cc[0], cc[1], cc[2], cc[3],
                         a[ms][0], a[ms][1], a[ms][2], a[ms][3],
                         bf[nc][0], bf[nc][1]);
            }
    }

    // epilogue: Z fp16, half2 = (o even, o odd)
#pragma unroll
    for (int ms = 0; ms < 4; ms++) {
        int m0 = MB0 + wm + ms * 16 + g;
#pragma unroll
        for (int nc = 0; nc < 8; nc++) {
            int opair = (o0 + wo + nc * 8) / 2 + t4;
            float* cc = acc[ms * 8 + nc];
            size_t zi = ((size_t)(t * 256 + opair)) * 16384;
            g_Z[zi + m0]     = __floats2half2_rn(cc[0], cc[1]);
            g_Z[zi + m0 + 8] = __floats2half2_rn(cc[2], cc[3]);
        }
    }
}

// ---------------- output transform: 4 tiles/thread ----------------
__global__ void __launch_bounds__(256) ot_kernel(float* __restrict__ out) {
    int idx = blockIdx.x * 256 + threadIdx.x;
    int q     = idx & 7;
    int ty    = (idx >> 3) & 31;
    int opair = (idx >> 8) & 255;
    int b     = idx >> 16;
    size_t m0 = (size_t)b * 1024 + ty * 32 + 4 * q;

    uint4 z[16];
#pragma unroll
    for (int t = 0; t < 16; t++)
        z[t] = *reinterpret_cast<const uint4*>(&g_Z[((size_t)t * 256 + opair) * 16384 + m0]);

    float dm[2];
    dm[0] = g_demod[b * 512 + 2 * opair];
    dm[1] = g_demod[b * 512 + 2 * opair + 1];

    float o[2][2][8];
#pragma unroll
    for (int dt = 0; dt < 4; dt++) {
        float2 F[16];
#pragma unroll
        for (int t = 0; t < 16; t++)
            F[t] = __half22float2(reinterpret_cast<const __half2*>(&z[t])[dt]);
#pragma unroll
        for (int ch = 0; ch < 2; ch++) {
            float M[16];
#pragma unroll
            for (int t = 0; t < 16; t++) M[t] = ch ? F[t].y : F[t].x;
            float T0[4], T1[4];
#pragma unroll
            for (int j = 0; j < 4; j++) {
                T0[j] = M[j] + M[4 + j] + M[8 + j];
                T1[j] = M[4 + j] - M[8 + j] - M[12 + j];
            }
            float d = dm[ch];
            o[ch][0][2 * dt]     = (T0[0] + T0[1] + T0[2]) * d;
            o[ch][0][2 * dt + 1] = (T0[1] - T0[2] - T0[3]) * d;
            o[ch][1][2 * dt]     = (T1[0] + T1[1] + T1[2]) * d;
            o[ch][1][2 * dt + 1] = (T1[1] - T1[2] - T1[3]) * d;
        }
    }

    float* base = out + ((size_t)b * 512 + 2 * opair) * 4096 + (2 * ty) * 64 + 8 * q;
#pragma unroll
    for (int ch = 0; ch < 2; ch++)
#pragma unroll
        for (int r = 0; r < 2; r++) {
            float* p = base + (size_t)ch * 4096 + r * 64;
            *reinterpret_cast<float4*>(p)     = make_float4(o[ch][r][0], o[ch][r][1],
                                                            o[ch][r][2], o[ch][r][3]);
            *reinterpret_cast<float4*>(p + 4) = make_float4(o[ch][r][4], o[ch][r][5],
                                                            o[ch][r][6], o[ch][r][7]);
        }
}

// ---------------- launch ----------------
extern "C" void kernel_launch(void* const* d_in, const int* in_sizes, int n_in,
                              void* d_out, int out_size) {
    const float* x      = (const float*)d_in[0];
    const float* w      = (const float*)d_in[1];
    const float* weight = (const float*)d_in[2];
    const float* mw     = (const float*)d_in[3];
    const float* mb     = (const float*)d_in[4];
    float* out = (float*)d_out;

    style_kernel<<<16, 512>>>(w, mw, mb);
    ut_kernel<<<512, 256>>>(weight);        // also produces g_wsq
    demod_kernel<<<1024, 256>>>();          // warp-per-(b,o) reduction
    vt_kernel<<<4096, 256>>>(x);

    int shmem = 4 * STGH * 4;   // 34816 B
    cudaFuncSetAttribute(wg_kernel, cudaFuncAttributeMaxDynamicSharedMemorySize, shmem);
    dim3 grid(128, 4, 16);   // (M/128, N/128, t)
    wg_kernel<<<grid, 128, shmem>>>();

    ot_kernel<<<4096, 256>>>(out);
}

// round 14
// speedup vs baseline: 1.2502x; 1.0195x over previous
#include <cuda_runtime.h>
#include <cuda_fp16.h>
#include <cstdint>

#define NB 16

static __device__ float   g_style[NB * 512];
static __device__ float   g_wsq[512 * 512];
static __device__ float   g_demod[NB * 512];
static __device__ __half2 g_V[(size_t)16 * 256 * 16384];  // [t][kk][m]
static __device__ __half2 g_U[(size_t)16 * 256 * 512];    // [t][kk][o]
static __device__ __half2 g_Z[(size_t)16 * 256 * 16384];  // [t][opair][m]

// ---------------- fused prep: blocks 0-15 style, blocks 16-271 ut(+wsq) ----------------
__global__ void __launch_bounds__(512) prep_kernel(const float* __restrict__ w,
                                                   const float* __restrict__ mw,
                                                   const float* __restrict__ mb,
                                                   const float* __restrict__ weight) {
    if (blockIdx.x < 16) {
        __shared__ float sw[512];
        int b = blockIdx.x, c = threadIdx.x;
        sw[c] = w[b * 512 + c];
        __syncthreads();
        float acc = 0.f;
        const float* row = mw + c * 512;
#pragma unroll 8
        for (int d = 0; d < 512; d++) acc += sw[d] * row[d];
        g_style[b * 512 + c] = acc * 0.04419417382415922f + mb[c];
        return;
    }
    int idx = (blockIdx.x - 16) * 512 + threadIdx.x;   // 131072
    int o = idx & 511, kk = idx >> 9;
    const float WG = 0.014731391274719739f;
    float u[2][4][4];
#pragma unroll
    for (int ch = 0; ch < 2; ch++) {
        const float* wp = weight + ((size_t)o * 512 + 2 * kk + ch) * 9;
        float tmp[4][3];
        float sq = 0.f;
#pragma unroll
        for (int c = 0; c < 3; c++) {
            float w0 = wp[c], w1 = wp[3 + c], w2 = wp[6 + c];
            sq += w0 * w0 + w1 * w1 + w2 * w2;
            tmp[0][c] = w0;
            tmp[1][c] = 0.5f * (w0 + w1 + w2);
            tmp[2][c] = 0.5f * (w0 - w1 + w2);
            tmp[3][c] = w2;
        }
        g_wsq[o * 512 + 2 * kk + ch] = sq;
#pragma unroll
        for (int i = 0; i < 4; i++) {
            float t0 = tmp[i][0], t1 = tmp[i][1], t2 = tmp[i][2];
            u[ch][i][0] = t0 * WG;
            u[ch][i][1] = 0.5f * (t0 + t1 + t2) * WG;
            u[ch][i][2] = 0.5f * (t0 - t1 + t2) * WG;
            u[ch][i][3] = t2 * WG;
        }
    }
#pragma unroll
    for (int t = 0; t < 16; t++)
        g_U[((size_t)t * 256 + kk) * 512 + o] =
            __floats2half2_rn(u[0][t >> 2][t & 3], u[1][t >> 2][t & 3]);
}

// demod: one warp per (b,o), shfl reduction
__global__ void demod_kernel() {
    int wid = blockIdx.x * 8 + (threadIdx.x >> 5);
    int lane = threadIdx.x & 31;
    int b = wid & 15, o = wid >> 4;
    const float* wq = g_wsq + o * 512;
    const float* st = g_style + b * 512;
    float s = 0.f;
#pragma unroll
    for (int i = 0; i < 16; i++) {
        int c = lane + i * 32;
        float t = st[c];
        s += wq[c] * t * t;
    }
#pragma unroll
    for (int d = 16; d > 0; d >>= 1)
        s += __shfl_xor_sync(0xFFFFFFFFu, s, d);
    if (lane == 0)
        g_demod[b * 512 + o] = rsqrtf(s * (1.f / 4608.f) + 1e-8f);
}

// ---------------- V = B^T (style*x) B : 4 tiles/thread ----------------
__global__ void __launch_bounds__(256) vt_kernel(const float* __restrict__ x) {
    int idx = blockIdx.x * 256 + threadIdx.x;
    int q  = idx & 7;
    int ty = (idx >> 3) & 31;
    int kk = (idx >> 8) & 255;
    int b  = idx >> 16;
    float s[2];
    s[0] = g_style[b * 512 + 2 * kk];
    s[1] = g_style[b * 512 + 2 * kk + 1];

    float f0[16][4];
    __half2 hv[16][4];

#pragma unroll
    for (int ch = 0; ch < 2; ch++) {
        const float* xp = x + ((size_t)(b * 512 + 2 * kk + ch)) * 4096;
        float d[4][10];
        int y0 = 2 * ty - 1;
        int xl = 8 * q - 1;
#pragma unroll
        for (int r = 0; r < 4; r++) {
            int y = y0 + r;
            bool vy = (y >= 0) && (y < 64);
            const float* row = xp + y * 64;
            float4 A = make_float4(0.f, 0.f, 0.f, 0.f), B = A;
            if (vy) {
                A = *reinterpret_cast<const float4*>(row + 8 * q);
                B = *reinterpret_cast<const float4*>(row + 8 * q + 4);
            }
            float sc = s[ch];
            d[r][0] = (vy && q > 0) ? row[xl] * sc : 0.f;
            d[r][1] = A.x * sc; d[r][2] = A.y * sc; d[r][3] = A.z * sc; d[r][4] = A.w * sc;
            d[r][5] = B.x * sc; d[r][6] = B.y * sc; d[r][7] = B.z * sc; d[r][8] = B.w * sc;
            d[r][9] = (vy && q < 7) ? row[8 * q + 8] * sc : 0.f;
        }
        float p[4][10];
#pragma unroll
        for (int c = 0; c < 10; c++) {
            p[0][c] = d[0][c] - d[2][c];
            p[1][c] = d[1][c] + d[2][c];
            p[2][c] = d[2][c] - d[1][c];
            p[3][c] = d[1][c] - d[3][c];
        }
#pragma unroll
        for (int dt = 0; dt < 4; dt++) {
            int cl = 2 * dt;
#pragma unroll
            for (int i = 0; i < 4; i++) {
                float v0 = p[i][cl]     - p[i][cl + 2];
                float v1 = p[i][cl + 1] + p[i][cl + 2];
                float v2 = p[i][cl + 2] - p[i][cl + 1];
                float v3 = p[i][cl + 1] - p[i][cl + 3];
                if (ch == 0) {
                    f0[4 * i + 0][dt] = v0; f0[4 * i + 1][dt] = v1;
                    f0[4 * i + 2][dt] = v2; f0[4 * i + 3][dt] = v3;
                } else {
                    hv[4 * i + 0][dt] = __floats2half2_rn(f0[4 * i + 0][dt], v0);
                    hv[4 * i + 1][dt] = __floats2half2_rn(f0[4 * i + 1][dt], v1);
                    hv[4 * i + 2][dt] = __floats2half2_rn(f0[4 * i + 2][dt], v2);
                    hv[4 * i + 3][dt] = __floats2half2_rn(f0[4 * i + 3][dt], v3);
                }
            }
        }
    }
    size_t m0 = (size_t)b * 1024 + ty * 32 + 4 * q;
#pragma unroll
    for (int t = 0; t < 16; t++)
        *reinterpret_cast<uint4*>(&g_V[((size_t)t * 256 + kk) * 16384 + m0]) =
            *reinterpret_cast<const uint4*>(hv[t]);
}

// ---------------- Winograd GEMM: m64n64 warps, 128-thread CTAs ----------------
__device__ __forceinline__ void mma16816(float& c0, float& c1, float& c2, float& c3,
                                         uint32_t a0, uint32_t a1, uint32_t a2, uint32_t a3,
                                         uint32_t b0, uint32_t b1) {
    asm volatile(
        "mma.sync.aligned.m16n8k16.row.col.f32.f16.f16.f32 "
        "{%0,%1,%2,%3}, {%4,%5,%6,%7}, {%8,%9}, {%0,%1,%2,%3};\n"
        : "+f"(c0), "+f"(c1), "+f"(c2), "+f"(c3)
        : "r"(a0), "r"(a1), "r"(a2), "r"(a3), "r"(b0), "r"(b1));
}
__device__ __forceinline__ void cp16(uint32_t dst, const void* src) {
    asm volatile("cp.async.cg.shared.global [%0], [%1], 16;\n" :: "r"(dst), "l"(src));
}
__device__ __forceinline__ void cp_commit() {
    asm volatile("cp.async.commit_group;\n" ::: "memory");
}

#define AS_K 136
#define BS_K 136
#define STGH (8 * AS_K + 8 * BS_K)   // 2176 half2 = 8704 B per stage

__global__ void __launch_bounds__(128) wg_kernel() {
    extern __shared__ __align__(16) __half2 sm[];
    const int t   = blockIdx.z;
    const int o0  = blockIdx.y * 128;
    const int MB0 = blockIdx.x * 128;
    const int tid = threadIdx.x, w = tid >> 5, lane = tid & 31;
    const int g = lane >> 2, t4 = lane & 3;
    const int wm = (w & 1) * 64;
    const int wo = (w >> 1) * 64;
    const uint32_t sb = (uint32_t)__cvta_generic_to_shared(sm);

    float acc[32][4];
#pragma unroll
    for (int i = 0; i < 32; i++)
#pragma unroll
        for (int j = 0; j < 4; j++) acc[i][j] = 0.f;

    auto load = [&](int kc, int st) {
        uint32_t base = sb + (uint32_t)(st * STGH) * 4u;
#pragma unroll
        for (int i = 0; i < 2; i++) {
            int id2 = tid + i * 128;
            int kkL = id2 >> 5, v = id2 & 31;
            cp16(base + (uint32_t)(kkL * AS_K) * 4u + v * 16u,
                 g_V + ((size_t)(t * 256 + kc * 8 + kkL)) * 16384 + MB0 + v * 4);
        }
#pragma unroll
        for (int i = 0; i < 2; i++) {
            int id2 = tid + i * 128;
            int kkL = id2 >> 5, v = id2 & 31;
            cp16(base + (uint32_t)(8 * AS_K + kkL * BS_K) * 4u + v * 16u,
                 g_U + ((size_t)(t * 256 + kc * 8 + kkL)) * 512 + o0 + v * 4);
        }
    };
    load(0, 0); cp_commit();
    load(1, 1); cp_commit();
    load(2, 2); cp_commit();

#pragma unroll 1
    for (int c = 0; c < 32; c++) {
        if (c <= 29)      asm volatile("cp.async.wait_group 2;\n" ::: "memory");
        else if (c == 30) asm volatile("cp.async.wait_group 1;\n" ::: "memory");
        else              asm volatile("cp.async.wait_group 0;\n" ::: "memory");
        __syncthreads();
        if (c + 3 < 32) { load(c + 3, (c + 3) & 3); cp_commit(); }

        const __half2* As = sm + (c & 3) * STGH;
        const __half2* Bs = As + 8 * AS_K;

        uint32_t a[4][4];
#pragma unroll
        for (int ms = 0; ms < 4; ms++) {
            const __half2* ab = As + t4 * AS_K + wm + ms * 16 + g;
            a[ms][0] = *reinterpret_cast<const uint32_t*>(ab);
            a[ms][1] = *reinterpret_cast<const uint32_t*>(ab + 8);
            a[ms][2] = *reinterpret_cast<const uint32_t*>(ab + 4 * AS_K);
            a[ms][3] = *reinterpret_cast<const uint32_t*>(ab + 4 * AS_K + 8);
        }
        uint32_t bf[8][2];
#pragma unroll
        for (int nc = 0; nc < 8; nc++) {
            const __half2* bb = Bs + t4 * BS_K + wo + nc * 8 + g;
            bf[nc][0] = *reinterpret_cast<const uint32_t*>(bb);
            bf[nc][1] = *reinterpret_cast<const uint32_t*>(bb + 4 * BS_K);
        }
#pragma unroll
        for (int nc = 0; nc < 8; nc++)
#pragma unroll
            for (int ms = 0; ms < 4; ms++) {
                float* cc = acc[ms * 8 + nc];
                mma16816(cc[0], cc[1], cc[2], cc[3],
                         a[ms][0], a[ms][1], a[ms][2], a[ms][3],
                         bf[nc][0], bf[nc][1]);
            }
    }

#pragma unroll
    for (int ms = 0; ms < 4; ms++) {
        int m0 = MB0 + wm + ms * 16 + g;
#pragma unroll
        for (int nc = 0; nc < 8; nc++) {
            int opair = (o0 + wo + nc * 8) / 2 + t4;
            float* cc = acc[ms * 8 + nc];
            size_t zi = ((size_t)(t * 256 + opair)) * 16384;
            g_Z[zi + m0]     = __floats2half2_rn(cc[0], cc[1]);
            g_Z[zi + m0 + 8] = __floats2half2_rn(cc[2], cc[3]);
        }
    }
}

// ---------------- output transform: 2 tiles/thread (higher occupancy) ----------------
__global__ void __launch_bounds__(256) ot_kernel(float* __restrict__ out) {
    int idx = blockIdx.x * 256 + threadIdx.x;   // 2,097,152
    int q     = idx & 15;
    int ty    = (idx >> 4) & 31;
    int opair = (idx >> 9) & 255;
    int b     = idx >> 17;
    size_t m0 = (size_t)b * 1024 + ty * 32 + 2 * q;

    uint2 z[16];
#pragma unroll
    for (int t = 0; t < 16; t++)
        z[t] = *reinterpret_cast<const uint2*>(&g_Z[((size_t)t * 256 + opair) * 16384 + m0]);

    float dm[2];
    dm[0] = g_demod[b * 512 + 2 * opair];
    dm[1] = g_demod[b * 512 + 2 * opair + 1];

    float o[2][2][4];
#pragma unroll
    for (int dt = 0; dt < 2; dt++) {
        float2 F[16];
#pragma unroll
        for (int t = 0; t < 16; t++)
            F[t] = __half22float2(reinterpret_cast<const __half2*>(&z[t])[dt]);
#pragma unroll
        for (int ch = 0; ch < 2; ch++) {
            float M[16];
#pragma unroll
            for (int t = 0; t < 16; t++) M[t] = ch ? F[t].y : F[t].x;
            float T0[4], T1[4];
#pragma unroll
            for (int j = 0; j < 4; j++) {
                T0[j] = M[j] + M[4 + j] + M[8 + j];
                T1[j] = M[4 + j] - M[8 + j] - M[12 + j];
            }
            float d = dm[ch];
            o[ch][0][2 * dt]     = (T0[0] + T0[1] + T0[2]) * d;
            o[ch][0][2 * dt + 1] = (T0[1] - T0[2] - T0[3]) * d;
            o[ch][1][2 * dt]     = (T1[0] + T1[1] + T1[2]) * d;
            o[ch][1][2 * dt + 1] = (T1[1] - T1[2] - T1[3]) * d;
        }
    }

    float* base = out + ((size_t)b * 512 + 2 * opair) * 4096 + (2 * ty) * 64 + 4 * q;
#pragma unroll
    for (int ch = 0; ch < 2; ch++)
#pragma unroll
        for (int r = 0; r < 2; r++) {
            float* p = base + (size_t)ch * 4096 + r * 64;
            *reinterpret_cast<float4*>(p) = make_float4(o[ch][r][0], o[ch][r][1],
                                                        o[ch][r][2], o[ch][r][3]);
        }
}

// ---------------- launch ----------------
extern "C" void kernel_launch(void* const* d_in, const int* in_sizes, int n_in,
                              void* d_out, int out_size) {
    const float* x      = (const float*)d_in[0];
    const float* w      = (const float*)d_in[1];
    const float* weight = (const float*)d_in[2];
    const float* mw     = (const float*)d_in[3];
    const float* mb     = (const float*)d_in[4];
    float* out = (float*)d_out;

    prep_kernel<<<272, 512>>>(w, mw, mb, weight);   // style + ut + wsq fused
    demod_kernel<<<1024, 256>>>();
    vt_kernel<<<4096, 256>>>(x);

    int shmem = 4 * STGH * 4;   // 34816 B
    cudaFuncSetAttribute(wg_kernel, cudaFuncAttributeMaxDynamicSharedMemorySize, shmem);
    dim3 grid(128, 4, 16);   // (M/128, N/128, t)
    wg_kernel<<<grid, 128, shmem>>>();

    ot_kernel<<<8192, 256>>>(out);
}

// round 15
// speedup vs baseline: 1.2663x; 1.0129x over previous
#include <cuda_runtime.h>
#include <cuda_fp16.h>
#include <cstdint>

#define NB 16

static __device__ float   g_style[NB * 512];
static __device__ float   g_wsq[512 * 512];
static __device__ float   g_demod[NB * 512];
static __device__ __half2 g_V[(size_t)16 * 256 * 16384];  // [t][kk][m]
static __device__ __half2 g_U[(size_t)16 * 256 * 512];    // [t][kk][o]
static __device__ __half2 g_Z[(size_t)16 * 256 * 16384];  // [t][opair][m]

// ---------------- fused prep: blocks 0-15 style, blocks 16-271 ut(+wsq) ----------------
__global__ void __launch_bounds__(512) prep_kernel(const float* __restrict__ w,
                                                   const float* __restrict__ mw,
                                                   const float* __restrict__ mb,
                                                   const float* __restrict__ weight) {
    if (blockIdx.x < 16) {
        __shared__ float sw[512];
        int b = blockIdx.x, c = threadIdx.x;
        sw[c] = w[b * 512 + c];
        __syncthreads();
        float acc = 0.f;
        const float* row = mw + c * 512;
#pragma unroll 8
        for (int d = 0; d < 512; d++) acc += sw[d] * row[d];
        g_style[b * 512 + c] = acc * 0.04419417382415922f + mb[c];
        return;
    }
    int idx = (blockIdx.x - 16) * 512 + threadIdx.x;
    int o = idx & 511, kk = idx >> 9;
    const float WG = 0.014731391274719739f;
    float u[2][4][4];
#pragma unroll
    for (int ch = 0; ch < 2; ch++) {
        const float* wp = weight + ((size_t)o * 512 + 2 * kk + ch) * 9;
        float tmp[4][3];
        float sq = 0.f;
#pragma unroll
        for (int c = 0; c < 3; c++) {
            float w0 = wp[c], w1 = wp[3 + c], w2 = wp[6 + c];
            sq += w0 * w0 + w1 * w1 + w2 * w2;
            tmp[0][c] = w0;
            tmp[1][c] = 0.5f * (w0 + w1 + w2);
            tmp[2][c] = 0.5f * (w0 - w1 + w2);
            tmp[3][c] = w2;
        }
        g_wsq[o * 512 + 2 * kk + ch] = sq;
#pragma unroll
        for (int i = 0; i < 4; i++) {
            float t0 = tmp[i][0], t1 = tmp[i][1], t2 = tmp[i][2];
            u[ch][i][0] = t0 * WG;
            u[ch][i][1] = 0.5f * (t0 + t1 + t2) * WG;
            u[ch][i][2] = 0.5f * (t0 - t1 + t2) * WG;
            u[ch][i][3] = t2 * WG;
        }
    }
#pragma unroll
    for (int t = 0; t < 16; t++)
        g_U[((size_t)t * 256 + kk) * 512 + o] =
            __floats2half2_rn(u[0][t >> 2][t & 3], u[1][t >> 2][t & 3]);
}

// demod: one warp per (b,o)
__global__ void demod_kernel() {
    int wid = blockIdx.x * 8 + (threadIdx.x >> 5);
    int lane = threadIdx.x & 31;
    int b = wid & 15, o = wid >> 4;
    const float* wq = g_wsq + o * 512;
    const float* st = g_style + b * 512;
    float s = 0.f;
#pragma unroll
    for (int i = 0; i < 16; i++) {
        int c = lane + i * 32;
        float t = st[c];
        s += wq[c] * t * t;
    }
#pragma unroll
    for (int d = 16; d > 0; d >>= 1)
        s += __shfl_xor_sync(0xFFFFFFFFu, s, d);
    if (lane == 0)
        g_demod[b * 512 + o] = rsqrtf(s * (1.f / 4608.f) + 1e-8f);
}

// ---------------- V = B^T (style*x) B : 4 tiles/thread ----------------
__global__ void __launch_bounds__(256) vt_kernel(const float* __restrict__ x) {
    int idx = blockIdx.x * 256 + threadIdx.x;
    int q  = idx & 7;
    int ty = (idx >> 3) & 31;
    int kk = (idx >> 8) & 255;
    int b  = idx >> 16;
    float s[2];
    s[0] = g_style[b * 512 + 2 * kk];
    s[1] = g_style[b * 512 + 2 * kk + 1];

    float f0[16][4];
    __half2 hv[16][4];

#pragma unroll
    for (int ch = 0; ch < 2; ch++) {
        const float* xp = x + ((size_t)(b * 512 + 2 * kk + ch)) * 4096;
        float d[4][10];
        int y0 = 2 * ty - 1;
        int xl = 8 * q - 1;
#pragma unroll
        for (int r = 0; r < 4; r++) {
            int y = y0 + r;
            bool vy = (y >= 0) && (y < 64);
            const float* row = xp + y * 64;
            float4 A = make_float4(0.f, 0.f, 0.f, 0.f), B = A;
            if (vy) {
                A = *reinterpret_cast<const float4*>(row + 8 * q);
                B = *reinterpret_cast<const float4*>(row + 8 * q + 4);
            }
            float sc = s[ch];
            d[r][0] = (vy && q > 0) ? row[xl] * sc : 0.f;
            d[r][1] = A.x * sc; d[r][2] = A.y * sc; d[r][3] = A.z * sc; d[r][4] = A.w * sc;
            d[r][5] = B.x * sc; d[r][6] = B.y * sc; d[r][7] = B.z * sc; d[r][8] = B.w * sc;
            d[r][9] = (vy && q < 7) ? row[8 * q + 8] * sc : 0.f;
        }
        float p[4][10];
#pragma unroll
        for (int c = 0; c < 10; c++) {
            p[0][c] = d[0][c] - d[2][c];
            p[1][c] = d[1][c] + d[2][c];
            p[2][c] = d[2][c] - d[1][c];
            p[3][c] = d[1][c] - d[3][c];
        }
#pragma unroll
        for (int dt = 0; dt < 4; dt++) {
            int cl = 2 * dt;
#pragma unroll
            for (int i = 0; i < 4; i++) {
                float v0 = p[i][cl]     - p[i][cl + 2];
                float v1 = p[i][cl + 1] + p[i][cl + 2];
                float v2 = p[i][cl + 2] - p[i][cl + 1];
                float v3 = p[i][cl + 1] - p[i][cl + 3];
                if (ch == 0) {
                    f0[4 * i + 0][dt] = v0; f0[4 * i + 1][dt] = v1;
                    f0[4 * i + 2][dt] = v2; f0[4 * i + 3][dt] = v3;
                } else {
                    hv[4 * i + 0][dt] = __floats2half2_rn(f0[4 * i + 0][dt], v0);
                    hv[4 * i + 1][dt] = __floats2half2_rn(f0[4 * i + 1][dt], v1);
                    hv[4 * i + 2][dt] = __floats2half2_rn(f0[4 * i + 2][dt], v2);
                    hv[4 * i + 3][dt] = __floats2half2_rn(f0[4 * i + 3][dt], v3);
                }
            }
        }
    }
    size_t m0 = (size_t)b * 1024 + ty * 32 + 4 * q;
#pragma unroll
    for (int t = 0; t < 16; t++)
        *reinterpret_cast<uint4*>(&g_V[((size_t)t * 256 + kk) * 16384 + m0]) =
            *reinterpret_cast<const uint4*>(hv[t]);
}

// ---------------- Winograd GEMM: m64n64 warps, K-chunk = 32 (16 kk rows/stage) ----------
__device__ __forceinline__ void mma16816(float& c0, float& c1, float& c2, float& c3,
                                         uint32_t a0, uint32_t a1, uint32_t a2, uint32_t a3,
                                         uint32_t b0, uint32_t b1) {
    asm volatile(
        "mma.sync.aligned.m16n8k16.row.col.f32.f16.f16.f32 "
        "{%0,%1,%2,%3}, {%4,%5,%6,%7}, {%8,%9}, {%0,%1,%2,%3};\n"
        : "+f"(c0), "+f"(c1), "+f"(c2), "+f"(c3)
        : "r"(a0), "r"(a1), "r"(a2), "r"(a3), "r"(b0), "r"(b1));
}
__device__ __forceinline__ void cp16(uint32_t dst, const void* src) {
    asm volatile("cp.async.cg.shared.global [%0], [%1], 16;\n" :: "r"(dst), "l"(src));
}
__device__ __forceinline__ void cp_commit() {
    asm volatile("cp.async.commit_group;\n" ::: "memory");
}

#define AS_K 136
#define BS_K 136
#define STGH (16 * AS_K + 16 * BS_K)   // 4352 half2 = 17408 B per stage

__global__ void __launch_bounds__(128) wg_kernel() {
    extern __shared__ __align__(16) __half2 sm[];
    const int t   = blockIdx.z;
    const int o0  = blockIdx.y * 128;
    const int MB0 = blockIdx.x * 128;
    const int tid = threadIdx.x, w = tid >> 5, lane = tid & 31;
    const int g = lane >> 2, t4 = lane & 3;
    const int wm = (w & 1) * 64;
    const int wo = (w >> 1) * 64;
    const uint32_t sb = (uint32_t)__cvta_generic_to_shared(sm);

    float acc[32][4];
#pragma unroll
    for (int i = 0; i < 32; i++)
#pragma unroll
        for (int j = 0; j < 4; j++) acc[i][j] = 0.f;

    // one chunk = 16 kk rows (32 input-pair channels); 16 chunks total
    auto load = [&](int kc, int st) {
        uint32_t base = sb + (uint32_t)(st * STGH) * 4u;
#pragma unroll
        for (int i = 0; i < 4; i++) {                       // A: 512 vec16
            int id2 = tid + i * 128;
            int kkL = id2 >> 5, v = id2 & 31;
            cp16(base + (uint32_t)(kkL * AS_K) * 4u + v * 16u,
                 g_V + ((size_t)(t * 256 + kc * 16 + kkL)) * 16384 + MB0 + v * 4);
        }
#pragma unroll
        for (int i = 0; i < 4; i++) {                       // B: 512 vec16
            int id2 = tid + i * 128;
            int kkL = id2 >> 5, v = id2 & 31;
            cp16(base + (uint32_t)(16 * AS_K + kkL * BS_K) * 4u + v * 16u,
                 g_U + ((size_t)(t * 256 + kc * 16 + kkL)) * 512 + o0 + v * 4);
        }
    };
    load(0, 0); cp_commit();
    load(1, 1); cp_commit();
    load(2, 2); cp_commit();

#pragma unroll 1
    for (int c = 0; c < 16; c++) {
        if (c <= 13)      asm volatile("cp.async.wait_group 2;\n" ::: "memory");
        else if (c == 14) asm volatile("cp.async.wait_group 1;\n" ::: "memory");
        else              asm volatile("cp.async.wait_group 0;\n" ::: "memory");
        __syncthreads();
        if (c + 3 < 16) { load(c + 3, (c + 3) & 3); cp_commit(); }

        const __half2* As = sm + (c & 3) * STGH;
        const __half2* Bs = As + 16 * AS_K;

#pragma unroll
        for (int ks = 0; ks < 2; ks++) {        // two k16 halves; loads of ks=1 overlap mma of ks=0
            const int kr = ks * 8 + t4;
            uint32_t a[4][4];
#pragma unroll
            for (int ms = 0; ms < 4; ms++) {
                const __half2* ab = As + kr * AS_K + wm + ms * 16 + g;
                a[ms][0] = *reinterpret_cast<const uint32_t*>(ab);
                a[ms][1] = *reinterpret_cast<const uint32_t*>(ab + 8);
                a[ms][2] = *reinterpret_cast<const uint32_t*>(ab + 4 * AS_K);
                a[ms][3] = *reinterpret_cast<const uint32_t*>(ab + 4 * AS_K + 8);
            }
            uint32_t bf[8][2];
#pragma unroll
            for (int nc = 0; nc < 8; nc++) {
                const __half2* bb = Bs + kr * BS_K + wo + nc * 8 + g;
                bf[nc][0] = *reinterpret_cast<const uint32_t*>(bb);
                bf[nc][1] = *reinterpret_cast<const uint32_t*>(bb + 4 * BS_K);
            }
#pragma unroll
            for (int nc = 0; nc < 8; nc++)
#pragma unroll
                for (int ms = 0; ms < 4; ms++) {
                    float* cc = acc[ms * 8 + nc];
                    mma16816(cc[0], cc[1], cc[2], cc[3],
                             a[ms][0], a[ms][1], a[ms][2], a[ms][3],
                             bf[nc][0], bf[nc][1]);
                }
        }
    }

    // epilogue: Z fp16, half2 = (o even, o odd)
#pragma unroll
    for (int ms = 0; ms < 4; ms++) {
        int m0 = MB0 + wm + ms * 16 + g;
#pragma unroll
        for (int nc = 0; nc < 8; nc++) {
            int opair = (o0 + wo + nc * 8) / 2 + t4;
            float* cc = acc[ms * 8 + nc];
            size_t zi = ((size_t)(t * 256 + opair)) * 16384;
            g_Z[zi + m0]     = __floats2half2_rn(cc[0], cc[1]);
            g_Z[zi + m0 + 8] = __floats2half2_rn(cc[2], cc[3]);
        }
    }
}

// ---------------- output transform: 2 tiles/thread ----------------
__global__ void __launch_bounds__(256) ot_kernel(float* __restrict__ out) {
    int idx = blockIdx.x * 256 + threadIdx.x;
    int q     = idx & 15;
    int ty    = (idx >> 4) & 31;
    int opair = (idx >> 9) & 255;
    int b     = idx >> 17;
    size_t m0 = (size_t)b * 1024 + ty * 32 + 2 * q;

    uint2 z[16];
#pragma unroll
    for (int t = 0; t < 16; t++)
        z[t] = *reinterpret_cast<const uint2*>(&g_Z[((size_t)t * 256 + opair) * 16384 + m0]);

    float dm[2];
    dm[0] = g_demod[b * 512 + 2 * opair];
    dm[1] = g_demod[b * 512 + 2 * opair + 1];

    float o[2][2][4];
#pragma unroll
    for (int dt = 0; dt < 2; dt++) {
        float2 F[16];
#pragma unroll
        for (int t = 0; t < 16; t++)
            F[t] = __half22float2(reinterpret_cast<const __half2*>(&z[t])[dt]);
#pragma unroll
        for (int ch = 0; ch < 2; ch++) {
            float M[16];
#pragma unroll
            for (int t = 0; t < 16; t++) M[t] = ch ? F[t].y : F[t].x;
            float T0[4], T1[4];
#pragma unroll
            for (int j = 0; j < 4; j++) {
                T0[j] = M[j] + M[4 + j] + M[8 + j];
                T1[j] = M[4 + j] - M[8 + j] - M[12 + j];
            }
            float d = dm[ch];
            o[ch][0][2 * dt]     = (T0[0] + T0[1] + T0[2]) * d;
            o[ch][0][2 * dt + 1] = (T0[1] - T0[2] - T0[3]) * d;
            o[ch][1][2 * dt]     = (T1[0] + T1[1] + T1[2]) * d;
            o[ch][1][2 * dt + 1] = (T1[1] - T1[2] - T1[3]) * d;
        }
    }

    float* base = out + ((size_t)b * 512 + 2 * opair) * 4096 + (2 * ty) * 64 + 4 * q;
#pragma unroll
    for (int ch = 0; ch < 2; ch++)
#pragma unroll
        for (int r = 0; r < 2; r++) {
            float* p = base + (size_t)ch * 4096 + r * 64;
            *reinterpret_cast<float4*>(p) = make_float4(o[ch][r][0], o[ch][r][1],
                                                        o[ch][r][2], o[ch][r][3]);
        }
}

// ---------------- launch ----------------
extern "C" void kernel_launch(void* const* d_in, const int* in_sizes, int n_in,
                              void* d_out, int out_size) {
    const float* x      = (const float*)d_in[0];
    const float* w      = (const float*)d_in[1];
    const float* weight = (const float*)d_in[2];
    const float* mw     = (const float*)d_in[3];
    const float* mb     = (const float*)d_in[4];
    float* out = (float*)d_out;

    prep_kernel<<<272, 512>>>(w, mw, mb, weight);
    demod_kernel<<<1024, 256>>>();
    vt_kernel<<<4096, 256>>>(x);

    int shmem = 4 * STGH * 4;   // 69632 B
    cudaFuncSetAttribute(wg_kernel, cudaFuncAttributeMaxDynamicSharedMemorySize, shmem);
    dim3 grid(128, 4, 16);   // (M/128, N/128, t)
    wg_kernel<<<grid, 128, shmem>>>();

    ot_kernel<<<8192, 256>>>(out);
}